// round 11
// baseline (speedup 1.0000x reference)
#include <cuda_runtime.h>

#define LROW 16384
#define N1 8199
#define N2 4107
#define N3 2061
#define N4 1038
#define ROWS_MAX 2048

#define S1   8200
#define S1EO 8208      // split a1: even at +0, odd at +4104
#define A1O  4104

__device__ float g_a1[(size_t)ROWS_MAX * S1EO];
__device__ float g_d1[(size_t)ROWS_MAX * S1];
__device__ float g_thr[ROWS_MAX];

#define HLIT { \
    0.05441584224308161f,    0.3128715909144659f,    0.6756307362980128f, \
    0.5853546836548691f,    -0.015829105256023893f, -0.2840155429624281f, \
    0.00047248457399797254f, 0.128747426620186f,    -0.01736930100202211f, \
   -0.04408825393106472f,    0.013981027917015516f,  0.008746094047015655f, \
   -0.00487035299301066f,   -0.0003917403729959771f, 0.0006754494059985568f, \
   -0.00011747678400228192f }

__device__ __forceinline__ float softthr(float v, float thr) {
    float av = fabsf(v) - thr;
    return av > 0.f ? copysignf(av, v) : 0.f;
}

// polyphase DWT: 4 outputs r=0..3 from e[12], o[12]; uses e[r+s+1]
__device__ __forceinline__ void dwt4_eo(const float* e, const float* o,
                                        float* ca, float* cd)
{
    const float H[16] = HLIT;
    #pragma unroll
    for (int r = 0; r < 4; r++) {
        float a = 0.f, d = 0.f;
        #pragma unroll
        for (int s = 0; s < 8; s++) {
            float ev = e[r + s + 1], ov = o[r + s + 1];
            a = fmaf(H[2 * s],       ev, a);
            a = fmaf(H[2 * s + 1],   ov, a);
            d = fmaf(H[15 - 2 * s],  ev, d);
            d = fmaf(-H[14 - 2 * s], ov, d);
        }
        ca[r] = a; cd[r] = d;
    }
}

__device__ __forceinline__ float getA(const float* __restrict__ ae,
                                      const float* __restrict__ ao,
                                      int j, int n)
{
    j = (j < 0) ? (-1 - j) : j;
    j = (j >= n) ? (2 * n - 1 - j) : j;
    return (j & 1) ? ao[j >> 1] : ae[j >> 1];
}

__device__ __forceinline__ float2 dwt_scalar_eo(const float* __restrict__ ae,
                                                const float* __restrict__ ao,
                                                int n, int k)
{
    const float H[16] = HLIT;
    float a = 0.f, d = 0.f;
    #pragma unroll
    for (int t = 0; t < 16; t++) {
        float xv = getA(ae, ao, 2 * k + t - 14, n);
        a = fmaf(H[t], xv, a);
        d = fmaf((t & 1) ? -H[15 - t] : H[15 - t], xv, d);
    }
    return make_float2(a, d);
}

// ================= K_A: level-1 DWT (staged tiles) + median =================
__global__ void __launch_bounds__(256, 3)
k_fwd1(const float* __restrict__ x, float* __restrict__ a1g,
       float* __restrict__ d1g, float* __restrict__ thr_out)
{
    __shared__ alignas(16) float xe[2064];
    __shared__ alignas(16) float xo[2064];
    __shared__ int      s_hist[4][256];
    __shared__ unsigned s_pref;
    __shared__ int      s_rank;

    const int tid = threadIdx.x, lane = tid & 31, warp = tid >> 5;
    const int row = blockIdx.x;
    const float* xin = x + (size_t)row * LROW;
    float* pae = a1g + (size_t)row * S1EO;
    float* pao = pae + A1O;
    float* pd1 = d1g + (size_t)row * S1;

    #pragma unroll
    for (int rr = 0; rr < 4; rr++) s_hist[rr][tid] = 0;
    if (tid == 0) { s_pref = 0u; s_rank = (N1 - 1) / 2; }

    float dreg[32];
    for (int t = 0; t < 4; t++) {
        const int k0 = 2048 * t;
        const int base = 2 * k0 - 16;              // base+4112 <= 16384 always
        for (int q = tid; q < 1028; q += 256) {
            int g = base + 4 * q;
            float v0, v1, v2, v3;
            if (g >= 0) {
                float4 v = *reinterpret_cast<const float4*>(xin + g);
                v0 = v.x; v1 = v.y; v2 = v.z; v3 = v.w;
            } else {                                // t==0, q<4 only: left reflect
                int m0 = -1 - g;
                int m1 = (g + 1 < 0) ? (-2 - g) : (g + 1);
                int m2 = (g + 2 < 0) ? (-3 - g) : (g + 2);
                int m3 = (g + 3 < 0) ? (-4 - g) : (g + 3);
                v0 = xin[m0]; v1 = xin[m1]; v2 = xin[m2]; v3 = xin[m3];
            }
            *reinterpret_cast<float2*>(xe + 2 * q) = make_float2(v0, v2);
            *reinterpret_cast<float2*>(xo + 2 * q) = make_float2(v1, v3);
        }
        __syncthreads();
        #pragma unroll
        for (int c = 0; c < 2; c++) {
            int p0 = 1024 * c + 4 * tid;           // < 2048
            float e[12], o[12];
            #pragma unroll
            for (int j = 0; j < 3; j++) {
                float4 ve = *reinterpret_cast<const float4*>(xe + p0 + 4 * j);
                float4 vo = *reinterpret_cast<const float4*>(xo + p0 + 4 * j);
                e[4*j]=ve.x; e[4*j+1]=ve.y; e[4*j+2]=ve.z; e[4*j+3]=ve.w;
                o[4*j]=vo.x; o[4*j+1]=vo.y; o[4*j+2]=vo.z; o[4*j+3]=vo.w;
            }
            float ca[4], cd[4];
            dwt4_eo(e, o, ca, cd);
            int k = k0 + p0;
            *reinterpret_cast<float4*>(pd1 + k) = make_float4(cd[0], cd[1], cd[2], cd[3]);
            *reinterpret_cast<float2*>(pae + (k >> 1)) = make_float2(ca[0], ca[2]);
            *reinterpret_cast<float2*>(pao + (k >> 1)) = make_float2(ca[1], ca[3]);
            #pragma unroll
            for (int r = 0; r < 4; r++) dreg[8 * t + 4 * c + r] = cd[r];
        }
        __syncthreads();
    }
    // tail k = 8192..8198 from global (right reflect)
    float dtail = 0.f;
    if (tid < 7) {
        const float H[16] = HLIT;
        int k = 8192 + tid;
        float a = 0.f, d = 0.f;
        #pragma unroll
        for (int t2 = 0; t2 < 16; t2++) {
            int m = 2 * k + t2 - 14;
            if (m >= LROW) m = 2 * LROW - 1 - m;
            float xv = xin[m];
            a = fmaf(H[t2], xv, a);
            d = fmaf((t2 & 1) ? -H[15 - t2] : H[15 - t2], xv, d);
        }
        pd1[k] = d; dtail = d;
        if (k & 1) pao[k >> 1] = a; else pae[k >> 1] = a;
    }
    __syncthreads();

    // ---- exact median of |d1| via 4-round radix select on fp32 bits ----
    for (int b3 = 3; b3 >= 0; --b3) {
        const unsigned pref = s_pref;
        const int rank = s_rank;
        const int sh = b3 * 8;
        int* hist = s_hist[b3];
        #pragma unroll
        for (int j = 0; j < 32; j++) {
            unsigned u = __float_as_uint(fabsf(dreg[j]));
            bool mt = (b3 == 3) || ((u >> (sh + 8)) == pref);
            if (__any_sync(0xffffffffu, mt)) {
                unsigned bin = (u >> sh) & 255u;
                unsigned key = mt ? bin : 256u;
                unsigned grp = __match_any_sync(0xffffffffu, key);
                if (mt && lane == (__ffs(grp) - 1))
                    atomicAdd(&hist[bin], __popc(grp));
            }
        }
        if (tid < 7) {
            unsigned u = __float_as_uint(fabsf(dtail));
            if ((b3 == 3) || ((u >> (sh + 8)) == pref))
                atomicAdd(&hist[(u >> sh) & 255u], 1);
        }
        __syncthreads();
        if (warp == 0) {
            int base2 = lane * 8;
            int cnt[8], s = 0;
            #pragma unroll
            for (int q = 0; q < 8; q++) { cnt[q] = hist[base2 + q]; s += cnt[q]; }
            int incl = s;
            #pragma unroll
            for (int o2 = 1; o2 < 32; o2 <<= 1) {
                int t2 = __shfl_up_sync(0xffffffffu, incl, o2);
                if (lane >= o2) incl += t2;
            }
            int excl = incl - s;
            if (rank >= excl && rank < incl) {
                int acc = excl;
                #pragma unroll
                for (int q = 0; q < 8; q++) {
                    if (rank < acc + cnt[q]) {
                        s_pref = (pref << 8) | (unsigned)(base2 + q);
                        s_rank = rank - acc;
                        break;
                    }
                    acc += cnt[q];
                }
            }
        }
        __syncthreads();
    }
    if (tid == 0) {
        float med = __uint_as_float(s_pref);
        thr_out[row] = (med / 0.6745f) * 4.4054649f;   // * sqrt(2 ln 16384)
    }
}

// ====== K_B: DWT 2-4 (all in smem) + IDWT 4,3 + fused IDWT 2+1 -> out ======
// smem layout (floats):
#define B_A2E 0        // 2056 (pad 2064)
#define B_A2O 2064     // 2056 (pad 2064)
#define B_A3E 4128     // 1032 (pad 1040)
#define B_A3O 5168     // 1032 (pad 1040)
#define B_A4  6208     // 1040
#define B_D4  7248     // 1040
#define B_D2  8288     // 4108 (pad 4112)
#define B_D3  12400    // 2064
#define B_TOT 14464
// inv overlays: rec4 @ 0 (2062) ; rec3 @ 2064 (4108, ends 6172 < B_A4)
#define B_REC4 0
#define B_REC3 2064
#define SMB_BYTES (B_TOT * 4)

__device__ __forceinline__ void idwt4c(const float* a, const float* d, float* o) {
    const float H[16] = HLIT;
    #pragma unroll
    for (int pp = 0; pp < 4; pp++) {
        float e = 0.f, od = 0.f;
        #pragma unroll
        for (int s = 0; s < 8; s++) {
            e  = fmaf(H[14 - 2 * s], a[pp + s], e);
            e  = fmaf(H[2 * s + 1],  d[pp + s], e);
            od = fmaf(H[15 - 2 * s], a[pp + s], od);
            od = fmaf(-H[2 * s],     d[pp + s], od);
        }
        o[2*pp] = e; o[2*pp+1] = od;
    }
}

// smem->smem IDWT level with fused soft threshold (one strided sweep)
__device__ __forceinline__ void idwt_sm(const float* __restrict__ ca,
                                        const float* __restrict__ cd,
                                        int n, float thr,
                                        float* __restrict__ rec, int tid)
{
    int plim = n - 7;
    for (int p0 = 4 * tid; p0 < plim; p0 += 1024) {
        float a[12], d[12];
        if (p0 + 12 <= n) {
            #pragma unroll
            for (int j = 0; j < 3; j++) {
                float4 va = *reinterpret_cast<const float4*>(ca + p0 + 4 * j);
                float4 vd = *reinterpret_cast<const float4*>(cd + p0 + 4 * j);
                a[4*j] = va.x; a[4*j+1] = va.y; a[4*j+2] = va.z; a[4*j+3] = va.w;
                d[4*j] = vd.x; d[4*j+1] = vd.y; d[4*j+2] = vd.z; d[4*j+3] = vd.w;
            }
        } else {
            #pragma unroll
            for (int j = 0; j < 12; j++) {
                int q = p0 + j; if (q > n - 1) q = n - 1;
                a[j] = ca[q]; d[j] = cd[q];
            }
        }
        #pragma unroll
        for (int j = 0; j < 12; j++) d[j] = softthr(d[j], thr);
        float o[8];
        idwt4c(a, d, o);
        #pragma unroll
        for (int pp = 0; pp < 4; pp++)
            if (p0 + pp < plim) {
                rec[2 * (p0 + pp)]     = o[2*pp];
                rec[2 * (p0 + pp) + 1] = o[2*pp+1];
            }
    }
}

__global__ void __launch_bounds__(256, 3)
k_rest(const float* __restrict__ a1g, const float* __restrict__ d1g,
       const float* __restrict__ thr_arr, float* __restrict__ out)
{
    extern __shared__ float sm[];
    float* a2e = sm + B_A2E;  float* a2o = sm + B_A2O;
    float* a3e = sm + B_A3E;  float* a3o = sm + B_A3O;
    float* a4s = sm + B_A4;   float* d4s = sm + B_D4;
    float* d2s = sm + B_D2;   float* d3s = sm + B_D3;
    float* rec4 = sm + B_REC4;
    float* rec3 = sm + B_REC3;

    const int tid = threadIdx.x;
    const int row = blockIdx.x;
    const float thr = __ldg(thr_arr + row);
    const float* pae = a1g + (size_t)row * S1EO;
    const float* pao = pae + A1O;
    const float* pd1 = d1g + (size_t)row * S1;
    float* orow = out + (size_t)row * LROW;

    // ---- level 2: global split a1 -> smem split a2 + smem d2 ----
    #pragma unroll
    for (int c = 0; c < 4; c++) {
        int m0 = 1024 * c + 4 * tid;
        if (m0 >= 8) {
            float e[12], o[12];
            #pragma unroll
            for (int j = 0; j < 3; j++) {
                float4 ve = *reinterpret_cast<const float4*>(pae + m0 - 8 + 4 * j);
                float4 vo = *reinterpret_cast<const float4*>(pao + m0 - 8 + 4 * j);
                e[4*j]=ve.x; e[4*j+1]=ve.y; e[4*j+2]=ve.z; e[4*j+3]=ve.w;
                o[4*j]=vo.x; o[4*j+1]=vo.y; o[4*j+2]=vo.z; o[4*j+3]=vo.w;
            }
            float ca[4], cd[4];
            dwt4_eo(e, o, ca, cd);
            *reinterpret_cast<float4*>(d2s + m0) = make_float4(cd[0], cd[1], cd[2], cd[3]);
            *reinterpret_cast<float2*>(a2e + (m0 >> 1)) = make_float2(ca[0], ca[2]);
            *reinterpret_cast<float2*>(a2o + (m0 >> 1)) = make_float2(ca[1], ca[3]);
        } else {
            #pragma unroll
            for (int r = 0; r < 4; r++) {
                int m = m0 + r;
                float2 ad = dwt_scalar_eo(pae, pao, N1, m);
                d2s[m] = ad.y;
                if (m & 1) a2o[m >> 1] = ad.x; else a2e[m >> 1] = ad.x;
            }
        }
    }
    {   int m = 4096 + tid;
        if (m < N2) {
            float2 ad = dwt_scalar_eo(pae, pao, N1, m);
            d2s[m] = ad.y;
            if (m & 1) a2o[m >> 1] = ad.x; else a2e[m >> 1] = ad.x;
        }
    }
    __syncthreads();

    // ---- level 3: a2 -> a3 + d3 (smem) ----
    #pragma unroll
    for (int c = 0; c < 2; c++) {
        int m0 = 1024 * c + 4 * tid;
        if (m0 >= 8) {
            float e[12], o[12];
            #pragma unroll
            for (int j = 0; j < 3; j++) {
                float4 ve = *reinterpret_cast<const float4*>(a2e + m0 - 8 + 4 * j);
                float4 vo = *reinterpret_cast<const float4*>(a2o + m0 - 8 + 4 * j);
                e[4*j]=ve.x; e[4*j+1]=ve.y; e[4*j+2]=ve.z; e[4*j+3]=ve.w;
                o[4*j]=vo.x; o[4*j+1]=vo.y; o[4*j+2]=vo.z; o[4*j+3]=vo.w;
            }
            float ca[4], cd[4];
            dwt4_eo(e, o, ca, cd);
            *reinterpret_cast<float4*>(d3s + m0) = make_float4(cd[0], cd[1], cd[2], cd[3]);
            *reinterpret_cast<float2*>(a3e + (m0 >> 1)) = make_float2(ca[0], ca[2]);
            *reinterpret_cast<float2*>(a3o + (m0 >> 1)) = make_float2(ca[1], ca[3]);
        } else {
            #pragma unroll
            for (int r = 0; r < 4; r++) {
                int m = m0 + r;
                float2 ad = dwt_scalar_eo(a2e, a2o, N2, m);
                d3s[m] = ad.y;
                if (m & 1) a3o[m >> 1] = ad.x; else a3e[m >> 1] = ad.x;
            }
        }
    }
    {   int m = 2048 + tid;
        if (m < N3) {
            float2 ad = dwt_scalar_eo(a2e, a2o, N2, m);
            d3s[m] = ad.y;
            if (m & 1) a3o[m >> 1] = ad.x; else a3e[m >> 1] = ad.x;
        }
    }
    __syncthreads();

    // ---- level 4: a3 -> a4/d4 (smem, linear) ----
    {
        int m0 = 4 * tid;
        if (m0 >= 8) {
            float e[12], o[12];
            #pragma unroll
            for (int j = 0; j < 3; j++) {
                float4 ve = *reinterpret_cast<const float4*>(a3e + m0 - 8 + 4 * j);
                float4 vo = *reinterpret_cast<const float4*>(a3o + m0 - 8 + 4 * j);
                e[4*j]=ve.x; e[4*j+1]=ve.y; e[4*j+2]=ve.z; e[4*j+3]=ve.w;
                o[4*j]=vo.x; o[4*j+1]=vo.y; o[4*j+2]=vo.z; o[4*j+3]=vo.w;
            }
            float ca[4], cd[4];
            dwt4_eo(e, o, ca, cd);
            *reinterpret_cast<float4*>(a4s + m0) = make_float4(ca[0], ca[1], ca[2], ca[3]);
            *reinterpret_cast<float4*>(d4s + m0) = make_float4(cd[0], cd[1], cd[2], cd[3]);
        } else {
            #pragma unroll
            for (int r = 0; r < 4; r++) {
                int m = m0 + r;
                float2 ad = dwt_scalar_eo(a3e, a3o, N3, m);
                a4s[m] = ad.x; d4s[m] = ad.y;
            }
        }
        int m = 1024 + tid;
        if (m < N4) {
            float2 ad = dwt_scalar_eo(a3e, a3o, N3, m);
            a4s[m] = ad.x; d4s[m] = ad.y;
        }
    }
    __syncthreads();

    // ---- IDWT level 4: a4,d4 -> rec4 (overlays a2e region) ----
    idwt_sm(a4s, d4s, N4, thr, rec4, tid);
    __syncthreads();
    // ---- IDWT level 3: rec4, d3 -> rec3 ----
    idwt_sm(rec4, d3s, N3, thr, rec3, tid);
    __syncthreads();

    // ---- fused IDWT 2+1: rec3, d2 (smem), d1 (global) -> out ----
    {
        const float H[16] = HLIT;
        #pragma unroll
        for (int it = 0; it < 8; it++) {
            int p0 = 1024 * it + 4 * tid;           // [0, 8192)
            int u0 = p0 >> 1;                       // even
            float ru[14], du[14];
            #pragma unroll
            for (int j = 0; j < 7; j++) {
                float2 vr = *reinterpret_cast<const float2*>(rec3 + u0 + 2 * j);
                float2 vd = *reinterpret_cast<const float2*>(d2s  + u0 + 2 * j);
                ru[2*j] = vr.x; ru[2*j+1] = vr.y;
                du[2*j] = softthr(vd.x, thr); du[2*j+1] = softthr(vd.y, thr);
            }
            float rc[12];
            #pragma unroll
            for (int u = 0; u < 6; u++) {
                float ev = 0.f, ov = 0.f;
                #pragma unroll
                for (int s = 0; s < 8; s++) {
                    ev = fmaf(H[14 - 2 * s], ru[u + s], ev);
                    ev = fmaf(H[2 * s + 1],  du[u + s], ev);
                    ov = fmaf(H[15 - 2 * s], ru[u + s], ov);
                    ov = fmaf(-H[2 * s],     du[u + s], ov);
                }
                rc[2*u] = ev; rc[2*u+1] = ov;
            }
            float dv[12];
            #pragma unroll
            for (int j = 0; j < 3; j++) {
                float4 v = *reinterpret_cast<const float4*>(pd1 + p0 + 4 * j);
                dv[4*j]   = softthr(v.x, thr); dv[4*j+1] = softthr(v.y, thr);
                dv[4*j+2] = softthr(v.z, thr); dv[4*j+3] = softthr(v.w, thr);
            }
            float o8[8];
            idwt4c(rc, dv, o8);
            *reinterpret_cast<float4*>(orow + 2 * p0)     = make_float4(o8[0], o8[1], o8[2], o8[3]);
            *reinterpret_cast<float4*>(orow + 2 * p0 + 4) = make_float4(o8[4], o8[5], o8[6], o8[7]);
        }
    }
}

extern "C" void kernel_launch(void* const* d_in, const int* in_sizes, int n_in,
                              void* d_out, int out_size)
{
    const float* x = (const float*)d_in[0];
    float* out = (float*)d_out;
    int rows = in_sizes[0] / LROW;   // 2048

    float *a1, *d1, *thr;
    cudaGetSymbolAddress((void**)&a1, g_a1);
    cudaGetSymbolAddress((void**)&d1, g_d1);
    cudaGetSymbolAddress((void**)&thr, g_thr);

    cudaFuncSetAttribute(k_rest, cudaFuncAttributeMaxDynamicSharedMemorySize, SMB_BYTES);

    k_fwd1<<<rows, 256>>>(x, a1, d1, thr);
    k_rest<<<rows, 256, SMB_BYTES>>>(a1, d1, thr, out);
}

// round 12
// speedup vs baseline: 1.1069x; 1.1069x over previous
#include <cuda_runtime.h>

#define LROW 16384
#define N1 8199
#define N2 4107
#define N3 2061
#define N4 1038
#define ROWS_MAX 2048

// padded row strides (floats, 16B-multiples)
#define S1 8200
#define S2 4112
#define S3 2064
#define S4 1040

__device__ float g_a1[(size_t)ROWS_MAX * S1];
__device__ float g_d1[(size_t)ROWS_MAX * S1];
__device__ float g_a2[(size_t)ROWS_MAX * S2];
__device__ float g_d2[(size_t)ROWS_MAX * S2];
__device__ float g_a3[(size_t)ROWS_MAX * S3];
__device__ float g_d3[(size_t)ROWS_MAX * S3];
__device__ float g_a4[(size_t)ROWS_MAX * S4];
__device__ float g_d4[(size_t)ROWS_MAX * S4];
__device__ float g_thr[ROWS_MAX];

#define HLIT { \
    0.05441584224308161f,    0.3128715909144659f,    0.6756307362980128f, \
    0.5853546836548691f,    -0.015829105256023893f, -0.2840155429624281f, \
    0.00047248457399797254f, 0.128747426620186f,    -0.01736930100202211f, \
   -0.04408825393106472f,    0.013981027917015516f,  0.008746094047015655f, \
   -0.00487035299301066f,   -0.0003917403729959771f, 0.0006754494059985568f, \
   -0.00011747678400228192f }

__device__ __forceinline__ float softthr(float v, float thr) {
    float av = fabsf(v) - thr;
    return av > 0.f ? copysignf(av, v) : 0.f;
}

// 4 interleaved (a,d) outputs from window w[22] (w[2r+t])
__device__ __forceinline__ void dwt4(const float* w, float* o) {
    const float H[16] = HLIT;
    #pragma unroll
    for (int r = 0; r < 4; r++) {
        float a = 0.f, d = 0.f;
        #pragma unroll
        for (int t = 0; t < 16; t++) {
            float xv = w[2 * r + t];
            a = fmaf(H[t], xv, a);
            d = fmaf((t & 1) ? -H[15 - t] : H[15 - t], xv, d);
        }
        o[2 * r] = a; o[2 * r + 1] = d;
    }
}

// ============ K1: level-1 DWT + exact median (block per row) ================
__global__ void __launch_bounds__(256)
k_dwt1_med(const float* __restrict__ x, float* __restrict__ a1,
           float* __restrict__ d1, float* __restrict__ thr_out)
{
    __shared__ int      s_hist[4][8][256];   // per-round, per-warp (non-atomic)
    __shared__ unsigned s_pref;
    __shared__ int      s_rank;
    __shared__ float    s_tail[8];

    const float H[16] = HLIT;
    const int tid = threadIdx.x, lane = tid & 31, warp = tid >> 5;
    const float* xin = x  + (size_t)blockIdx.x * LROW;
    float* pa = a1 + (size_t)blockIdx.x * S1;
    float* pd = d1 + (size_t)blockIdx.x * S1;

    // pre-clear all round-histograms once
    {
        int* h = &s_hist[0][0][0];
        #pragma unroll
        for (int i = 0; i < 32; i++) h[256 * i + tid] = 0;
    }
    if (tid == 0) { s_pref = 0u; s_rank = (N1 - 1) / 2; }

    float dreg[32];
    #pragma unroll
    for (int c = 0; c < 8; c++) {
        float w[24];
        int base = 1024 * c + 4 * tid;          // < 8192 always
        int lo = 2 * base - 16;                 // 16B aligned; lo+24 <= 16384
        if (lo >= 0) {
            const float4* p = reinterpret_cast<const float4*>(xin + lo);
            #pragma unroll
            for (int j = 0; j < 6; j++) {
                float4 v = p[j];
                w[4*j] = v.x; w[4*j+1] = v.y; w[4*j+2] = v.z; w[4*j+3] = v.w;
            }
        } else {                                 // only c==0, tid<2
            #pragma unroll
            for (int j = 0; j < 24; j++) {
                int m = lo + j;
                m = (m < 0) ? (-1 - m) : m;
                w[j] = xin[m];
            }
        }
        float o[8];
        dwt4(w + 2, o);
        #pragma unroll
        for (int r = 0; r < 4; r++) dreg[4 * c + r] = o[2*r+1];
        *reinterpret_cast<float4*>(pa + base) = make_float4(o[0], o[2], o[4], o[6]);
        *reinterpret_cast<float4*>(pd + base) = make_float4(o[1], o[3], o[5], o[7]);
    }
    if (tid == 255) {                            // tail k = 8192..8198
        for (int e = 0; e < 7; e++) {
            int k = 8192 + e;
            float a = 0.f, d = 0.f;
            #pragma unroll
            for (int t = 0; t < 16; t++) {
                int m = 2 * k + t - 14;
                if (m >= LROW) m = 2 * LROW - 1 - m;
                float xv = xin[m];
                a = fmaf(H[t], xv, a);
                d = fmaf((t & 1) ? -H[15 - t] : H[15 - t], xv, d);
            }
            pa[k] = a; pd[k] = d; s_tail[e] = d;
        }
    }
    __syncthreads();
    const float dtail = (tid < 7) ? s_tail[tid] : 0.f;

    // ---- exact median of |d1|: 4-round radix select, per-warp histograms ----
    for (int b3 = 3; b3 >= 0; --b3) {
        const unsigned pref = s_pref;
        const int rank = s_rank;
        const int sh = b3 * 8;
        int (*hist)[256] = s_hist[b3];
        #pragma unroll
        for (int j = 0; j < 32; j++) {
            unsigned u = __float_as_uint(fabsf(dreg[j]));
            bool mt = (b3 == 3) || ((u >> (sh + 8)) == pref);
            if (__any_sync(0xffffffffu, mt)) {
                unsigned bin = (u >> sh) & 255u;
                unsigned key = mt ? bin : 256u;
                unsigned grp = __match_any_sync(0xffffffffu, key);
                if (mt && lane == (__ffs(grp) - 1))
                    hist[warp][bin] += __popc(grp);   // non-atomic: leaders hit distinct bins
            }
        }
        {   // 33rd element for threads 0..6 (tail values), warp 0 only does work
            bool has = (tid < 7);
            unsigned u = has ? __float_as_uint(fabsf(dtail)) : 0u;
            bool mt = has && ((b3 == 3) || ((u >> (sh + 8)) == pref));
            if (__any_sync(0xffffffffu, mt)) {
                unsigned bin = (u >> sh) & 255u;
                unsigned key = mt ? bin : 256u;
                unsigned grp = __match_any_sync(0xffffffffu, key);
                if (mt && lane == (__ffs(grp) - 1))
                    hist[warp][bin] += __popc(grp);
            }
        }
        __syncthreads();
        if (warp == 0) {                         // winner-bin reduction in warp 0
            int base2 = lane * 8;
            int cnt[8], s = 0;
            #pragma unroll
            for (int q = 0; q < 8; q++) {
                int c = 0;
                #pragma unroll
                for (int w2 = 0; w2 < 8; w2++) c += hist[w2][base2 + q];
                cnt[q] = c; s += c;
            }
            int incl = s;
            #pragma unroll
            for (int o2 = 1; o2 < 32; o2 <<= 1) {
                int t2 = __shfl_up_sync(0xffffffffu, incl, o2);
                if (lane >= o2) incl += t2;
            }
            int excl = incl - s;
            if (rank >= excl && rank < incl) {
                int acc = excl;
                #pragma unroll
                for (int q = 0; q < 8; q++) {
                    if (rank < acc + cnt[q]) {
                        s_pref = (pref << 8) | (unsigned)(base2 + q);
                        s_rank = rank - acc;
                        break;
                    }
                    acc += cnt[q];
                }
            }
        }
        __syncthreads();
    }
    if (tid == 0) {
        float med = __uint_as_float(s_pref);
        thr_out[blockIdx.x] = (med / 0.6745f) * 4.4054649f;  // * sqrt(2 ln 16384)
    }
}

// ===================== streaming DWT level (grid: x=positions/1024, y=rows) ====
__global__ void __launch_bounds__(256)
k_dwt(const float* __restrict__ in, float* __restrict__ oa, float* __restrict__ od,
      int n, int nout, int sin, int sout)
{
    int base = 4 * (blockIdx.x * 256 + threadIdx.x);
    if (base >= nout) return;
    const float* xin = in + (size_t)blockIdx.y * sin;
    float* pa = oa + (size_t)blockIdx.y * sout;
    float* pd = od + (size_t)blockIdx.y * sout;

    float w[24];
    int lo = 2 * base - 16;                      // 16B aligned
    if (lo >= 0 && lo + 24 <= n) {
        const float4* p = reinterpret_cast<const float4*>(xin + lo);
        #pragma unroll
        for (int j = 0; j < 6; j++) {
            float4 v = p[j];
            w[4*j] = v.x; w[4*j+1] = v.y; w[4*j+2] = v.z; w[4*j+3] = v.w;
        }
    } else {
        #pragma unroll
        for (int j = 0; j < 24; j++) {
            int m = lo + j;
            m = (m < 0) ? (-1 - m) : m;
            m = (m >= n) ? (2 * n - 1 - m) : m;
            w[j] = xin[m];
        }
    }
    float o[8];
    dwt4(w + 2, o);
    if (base + 4 <= nout) {
        *reinterpret_cast<float4*>(pa + base) = make_float4(o[0], o[2], o[4], o[6]);
        *reinterpret_cast<float4*>(pd + base) = make_float4(o[1], o[3], o[5], o[7]);
    } else {
        #pragma unroll
        for (int r = 0; r < 4; r++)
            if (base + r < nout) { pa[base + r] = o[2*r]; pd[base + r] = o[2*r+1]; }
    }
}

// ---------- idwt core: 4 pairs from a[12], d[12] ----------
__device__ __forceinline__ void idwt4(const float* a, const float* d, float* o) {
    const float H[16] = HLIT;
    #pragma unroll
    for (int pp = 0; pp < 4; pp++) {
        float e = 0.f, od = 0.f;
        #pragma unroll
        for (int s = 0; s < 8; s++) {
            e  = fmaf(H[14 - 2 * s], a[pp + s], e);
            e  = fmaf(H[2 * s + 1],  d[pp + s], e);
            od = fmaf(H[15 - 2 * s], a[pp + s], od);
            od = fmaf(-H[2 * s],     d[pp + s], od);
        }
        o[2*pp] = e; o[2*pp+1] = od;
    }
}

__device__ __forceinline__ void idwt_pass(const float* __restrict__ ca,
                                          const float* __restrict__ cd,
                                          int n, float thr,
                                          float* __restrict__ rec, int tid)
{
    int plim = n - 7;
    for (int p0 = 4 * tid; p0 < plim; p0 += 1024) {
        float a[12], d[12];
        if (p0 + 12 <= n) {
            #pragma unroll
            for (int j = 0; j < 3; j++) {
                float4 va = *reinterpret_cast<const float4*>(ca + p0 + 4 * j);
                float4 vd = *reinterpret_cast<const float4*>(cd + p0 + 4 * j);
                a[4*j] = va.x; a[4*j+1] = va.y; a[4*j+2] = va.z; a[4*j+3] = va.w;
                d[4*j] = vd.x; d[4*j+1] = vd.y; d[4*j+2] = vd.z; d[4*j+3] = vd.w;
            }
        } else {
            #pragma unroll
            for (int j = 0; j < 12; j++) {
                int q = p0 + j; if (q > n - 1) q = n - 1;
                a[j] = ca[q]; d[j] = cd[q];
            }
        }
        #pragma unroll
        for (int j = 0; j < 12; j++) d[j] = softthr(d[j], thr);
        float o[8];
        idwt4(a, d, o);
        if (p0 + 4 <= plim) {
            *reinterpret_cast<float4*>(rec + 2 * p0)     = make_float4(o[0], o[1], o[2], o[3]);
            *reinterpret_cast<float4*>(rec + 2 * p0 + 4) = make_float4(o[4], o[5], o[6], o[7]);
        } else {
            #pragma unroll
            for (int pp = 0; pp < 4; pp++)
                if (p0 + pp < plim) {
                    rec[2 * (p0 + pp)]     = o[2*pp];
                    rec[2 * (p0 + pp) + 1] = o[2*pp+1];
                }
        }
    }
}

// ============ K_inv: IDWT 4 -> 3 -> 2 -> 1, final level streams to out =======
#define SM_INV_FLOATS 12320
#define SM_INV_BYTES  (SM_INV_FLOATS * 4)
#define OFF_HI        8208

__global__ void __launch_bounds__(256, 4)
k_inv(const float* __restrict__ a4g, const float* __restrict__ d4g,
      const float* __restrict__ d3g, const float* __restrict__ d2g,
      const float* __restrict__ d1g, const float* __restrict__ thr_arr,
      float* __restrict__ out)
{
    extern __shared__ float sm[];
    float* REC = sm;             // flat 8200
    float* R4  = sm;             // overlays REC
    float* R3  = sm + OFF_HI;    // flat 4108

    const int tid = threadIdx.x;
    const int row = blockIdx.x;
    const float thr = __ldg(thr_arr + row);
    const float* pa4 = a4g + (size_t)row * S4;
    const float* pd4 = d4g + (size_t)row * S4;
    const float* pd3 = d3g + (size_t)row * S3;
    const float* pd2 = d2g + (size_t)row * S2;
    const float* pd1 = d1g + (size_t)row * S1;
    float* orow = out + (size_t)row * LROW;

    idwt_pass(pa4, pd4, N4, thr, R4, tid);   __syncthreads();  // R4 flat 2062
    idwt_pass(R4,  pd3, N3, thr, R3, tid);   __syncthreads();  // R3 flat 4108
    idwt_pass(R3,  pd2, N2, thr, REC, tid);  __syncthreads();  // REC flat 8200
    idwt_pass(REC, pd1, N1, thr, orow, tid);                   // 16384 -> out
}

static inline int gx_for(int work) { return (work + 1023) / 1024; }

extern "C" void kernel_launch(void* const* d_in, const int* in_sizes, int n_in,
                              void* d_out, int out_size)
{
    const float* x = (const float*)d_in[0];
    float* out = (float*)d_out;
    int rows = in_sizes[0] / LROW;   // 2048

    float *a1, *d1, *a2, *d2, *a3, *d3, *a4, *d4, *thr;
    cudaGetSymbolAddress((void**)&a1, g_a1);
    cudaGetSymbolAddress((void**)&d1, g_d1);
    cudaGetSymbolAddress((void**)&a2, g_a2);
    cudaGetSymbolAddress((void**)&d2, g_d2);
    cudaGetSymbolAddress((void**)&a3, g_a3);
    cudaGetSymbolAddress((void**)&d3, g_d3);
    cudaGetSymbolAddress((void**)&a4, g_a4);
    cudaGetSymbolAddress((void**)&d4, g_d4);
    cudaGetSymbolAddress((void**)&thr, g_thr);

    cudaFuncSetAttribute(k_inv, cudaFuncAttributeMaxDynamicSharedMemorySize, SM_INV_BYTES);

    k_dwt1_med<<<rows, 256>>>(x, a1, d1, thr);
    k_dwt<<<dim3(gx_for(N2), rows), 256>>>(a1, a2, d2, N1, N2, S1, S2);
    k_dwt<<<dim3(gx_for(N3), rows), 256>>>(a2, a3, d3, N2, N3, S2, S3);
    k_dwt<<<dim3(gx_for(N4), rows), 256>>>(a3, a4, d4, N3, N4, S3, S4);
    k_inv<<<rows, 256, SM_INV_BYTES>>>(a4, d4, d3, d2, d1, thr, out);
}